// round 12
// baseline (speedup 1.0000x reference)
#include <cuda_runtime.h>
#include <cstdint>

#define Bdim 16
#define Sdim 256
#define Hdim 768
#define Ddim 64
#define NSLOT 128
#define H4 (Hdim / 4)

// Partial-sum row offsets inside g_P (rows of 768 floats)
#define PV_OFF 0       // v partials (8 x 128)
#define P0A_OFF 1024   // v@Wz           (24 x 128)
#define P0B_OFF 4096   // bert_next@Wz   (12 x 128)
#define P1A_OFF 5632   // agg_z@Wf[:768] (24 x 128)
#define P1B_OFF 8704   // agg_d@Wf[768:] (2 x 128)
#define P2A_OFF 8960   // nrep@Wh[:768]  (24 x 128)
#define P2B_OFF 12032  // z@Wh[768:]     (12 x 128)
#define P_ROWS 13568

// Scratch (device globals; no allocation allowed)
__device__ __align__(16) float g_u1[Hdim];
__device__ __align__(16) float g_u2[Hdim];
__device__ float g_c[2];
__device__ __align__(16) float g_t2[Bdim * Sdim];
__device__ __align__(16) float g_attn[NSLOT * Sdim];
__device__ __align__(16) float g_Xv[NSLOT * Hdim];   // v (attn-weighted bert)
__device__ __align__(16) float g_Xn[NSLOT * Hdim];   // bert_next rows
__device__ __align__(16) float g_A[NSLOT * Hdim];    // agg_z
__device__ __align__(16) float g_Z[NSLOT * Hdim];    // zrow
__device__ __align__(16) float g_N[NSLOT * Hdim];    // nrep
__device__ __align__(16) float g_D64[NSLOT * Ddim];  // agg_d
__device__ __align__(16) float g_P[(size_t)P_ROWS * Hdim];
__device__ int g_valid[NSLOT];
__device__ int g_rowi[NSLOT];

#define ATT_SMEM_FLOATS (68 * 256 + 256 + 256 + 32 + 1024)

__global__ void __launch_bounds__(1024) k_att(const float*, const float*,
                                              const int*, const int*, const int*,
                                              const float*, const float*);

static cudaStream_t g_s2, g_s3;
static cudaEvent_t g_evFork, g_evCopy, g_evZ;
namespace {
struct HostInit {
  HostInit() {
    cudaStreamCreateWithFlags(&g_s2, cudaStreamNonBlocking);
    cudaStreamCreateWithFlags(&g_s3, cudaStreamNonBlocking);
    cudaEventCreateWithFlags(&g_evFork, cudaEventDisableTiming);
    cudaEventCreateWithFlags(&g_evCopy, cudaEventDisableTiming);
    cudaEventCreateWithFlags(&g_evZ, cudaEventDisableTiming);
    cudaFuncSetAttribute(k_att, cudaFuncAttributeMaxDynamicSharedMemorySize,
                         ATT_SMEM_FLOATS * 4);
  }
};
HostInit g_hostInit;
}  // namespace

__device__ __forceinline__ float warpReduceSum(float v) {
#pragma unroll
  for (int o = 16; o > 0; o >>= 1) v += __shfl_down_sync(0xffffffffu, v, o);
  return v;
}
__device__ __forceinline__ float warpReduceMax(float v) {
#pragma unroll
  for (int o = 16; o > 0; o >>= 1) v = fmaxf(v, __shfl_down_sync(0xffffffffu, v, o));
  return v;
}
__device__ __forceinline__ float blockReduceSum(float v, float* sm) {
  v = warpReduceSum(v);
  int w = threadIdx.x >> 5;
  if ((threadIdx.x & 31) == 0) sm[w] = v;
  __syncthreads();
  if (threadIdx.x < 8) {
    float x = sm[threadIdx.x];
#pragma unroll
    for (int o = 4; o > 0; o >>= 1) x += __shfl_down_sync(0xffu, x, o);
    if (threadIdx.x == 0) sm[0] = x;
  }
  __syncthreads();
  float r = sm[0];
  __syncthreads();
  return r;
}
__device__ __forceinline__ float blockReduceSum32(float v, float* sm) {
  v = warpReduceSum(v);
  int w = threadIdx.x >> 5;
  if ((threadIdx.x & 31) == 0) sm[w] = v;
  __syncthreads();
  if (threadIdx.x < 32) {
    float x = warpReduceSum(sm[threadIdx.x]);
    if (threadIdx.x == 0) sm[0] = x;
  }
  __syncthreads();
  float r = sm[0];
  __syncthreads();
  return r;
}
__device__ __forceinline__ float blockReduceMax32(float v, float* sm) {
  v = warpReduceMax(v);
  int w = threadIdx.x >> 5;
  if ((threadIdx.x & 31) == 0) sm[w] = v;
  __syncthreads();
  if (threadIdx.x < 32) {
    float x = warpReduceMax(sm[threadIdx.x]);
    if (threadIdx.x == 0) sm[0] = x;
  }
  __syncthreads();
  float r = sm[0];
  __syncthreads();
  return r;
}

// ---- packed f32x2 helpers ----
__device__ __forceinline__ unsigned long long splat2(float x) {
  unsigned long long r;
  asm("mov.b64 %0, {%1, %2};" : "=l"(r) : "f"(x), "f"(x));
  return r;
}
__device__ __forceinline__ void ffma2(unsigned long long& a, unsigned long long x,
                                      unsigned long long w) {
  asm("fma.rn.f32x2 %0, %1, %2, %0;" : "+l"(a) : "l"(x), "l"(w));
}
__device__ __forceinline__ float2 u2f(unsigned long long v) {
  float2 f;
  asm("mov.b64 {%0, %1}, %2;" : "=f"(f.x), "=f"(f.y) : "l"(v));
  return f;
}

// ---- cp.async helpers ----
__device__ __forceinline__ unsigned int saddr_of(const void* p) {
  return (unsigned int)__cvta_generic_to_shared(p);
}
__device__ __forceinline__ void cpasync16(unsigned int saddr, const void* g) {
  asm volatile("cp.async.ca.shared.global [%0], [%1], 16;" ::"r"(saddr), "l"(g));
}
__device__ __forceinline__ void cpasync_commit() {
  asm volatile("cp.async.commit_group;" ::: "memory");
}
__device__ __forceinline__ void cpasync_wait1() {
  asm volatile("cp.async.wait_group 1;" ::: "memory");
}
__device__ __forceinline__ void cpasync_wait0() {
  asm volatile("cp.async.wait_group 0;" ::: "memory");
}

__global__ void k_copy(const float4* __restrict__ src, float4* __restrict__ dst) {
  int i = blockIdx.x * 256 + threadIdx.x;
  dst[i] = src[i];
}

// bert_next gather: X_n[slot] = bert[b, (asp_s[b]+il+1) % S]. grid 128, block 192.
__global__ void __launch_bounds__(192) k_gather(const float* __restrict__ bert,
                                                const int* __restrict__ asp_s) {
  int slot = blockIdx.x;
  int b = slot >> 3, il = slot & 7;
  int i = (asp_s[b] + il) & (Sdim - 1);
  int inext = (i + 1) & (Sdim - 1);
  ((float4*)g_Xn)[slot * H4 + threadIdx.x] =
      ((const float4*)(bert + (size_t)(b * Sdim + inext) * Hdim))[threadIdx.x];
}

// u1/u2/c. grid 769, block 256.
__global__ void k_pre(const float* __restrict__ Wz, const float* __restrict__ bz,
                      const float* __restrict__ watt) {
  __shared__ float sm[8];
  int h = blockIdx.x, tid = threadIdx.x;
  float a1 = 0.f, a2 = 0.f;
  if (h < Hdim) {
    const float* wr = Wz + (size_t)h * Hdim;
    for (int k = tid; k < Hdim; k += 256) {
      float wv = wr[k];
      a1 = fmaf(wv, watt[k], a1);
      a2 = fmaf(wv, watt[Hdim + k], a2);
    }
  } else {
    for (int k = tid; k < Hdim; k += 256) {
      float bv = bz[k];
      a1 = fmaf(bv, watt[k], a1);
      a2 = fmaf(bv, watt[Hdim + k], a2);
    }
  }
  float r1 = blockReduceSum(a1, sm);
  float r2 = blockReduceSum(a2, sm);
  if (tid == 0) {
    if (h < Hdim) {
      g_u1[h] = r1;
      g_u2[h] = r2;
    } else {
      g_c[0] = r1;
      g_c[1] = r2;
    }
  }
}

// t2[r] = bert_row[r] @ u2 + bz.w2. grid 512, block 256.
__global__ void k_t2d(const float* __restrict__ bert) {
  int r = blockIdx.x * 8 + (threadIdx.x >> 5);
  int lane = threadIdx.x & 31;
  const float4* br = (const float4*)(bert + (size_t)r * Hdim);
  const float4* u24 = (const float4*)g_u2;
  float a = 0.f;
#pragma unroll
  for (int k = lane; k < H4; k += 32) {
    float4 bv = br[k];
    float4 uv = u24[k];
    a = fmaf(bv.x, uv.x, a);
    a = fmaf(bv.y, uv.y, a);
    a = fmaf(bv.z, uv.z, a);
    a = fmaf(bv.w, uv.w, a);
  }
  a = warpReduceSum(a);
  if (lane == 0) g_t2[r] = a + g_c[1];
}

// Attention: smem-staged dta row; logits + softmax + agg_d. grid (16,8), 1024 thr.
__global__ void __launch_bounds__(1024) k_att(
    const float* __restrict__ bert, const float* __restrict__ dta,
    const int* __restrict__ deprel, const int* __restrict__ asp_s,
    const int* __restrict__ asp_e, const float* __restrict__ w_att,
    const float* __restrict__ b_att) {
  extern __shared__ float dyns[];
  float* sD = dyns;
  float* sm_s = dyns + 68 * 256;
  float* sm_p = sm_s + 256;
  float* sm_red = sm_p + 256;
  float* sm_agg = sm_red + 32;

  int b = blockIdx.x, il = blockIdx.y;
  int slot = b * 8 + il;
  int tid = threadIdx.x;

  int start = asp_s[b], endi = asp_e[b];
  int i = start + il;
  bool active = (i <= endi) && (i < Sdim);
  const int* deprow = deprel + (size_t)(b * Sdim + (active ? i : 0)) * Sdim;
  int hasn = 0;
  if (active && tid < Sdim) hasn = (deprow[tid] > 0);
  int any = __syncthreads_or(hasn);
  if (!active || !any) {
    if (tid < Sdim) g_attn[slot * Sdim + tid] = 0.f;
    if (tid < Ddim) g_D64[slot * Ddim + tid] = 0.f;
    if (tid == 0) {
      g_valid[slot] = 0;
      g_rowi[slot] = 0;
    }
    return;
  }

  const float4* drow4 = (const float4*)(dta + (size_t)(b * Sdim + i) * Sdim * Ddim);
#pragma unroll
  for (int t = tid; t < 4096; t += 1024) {
    int j = t >> 4, q = t & 15;
    cpasync16(saddr_of(sD + j * 68 + q * 4), drow4 + t);
  }
  cpasync_commit();

  int inext = (i + 1) & (Sdim - 1);
  const float* bi = bert + (size_t)(b * Sdim + inext) * Hdim;

  float a = (tid < Hdim) ? bi[tid] * g_u1[tid] : 0.f;
  float s1 = blockReduceSum32(a, sm_red);
  float base = s1 + g_c[0] + b_att[0];

  cpasync_wait0();
  __syncthreads();

  {
    int j = tid >> 2, q = tid & 3;
    const float4* dj = (const float4*)(sD + j * 68) + q * 4;
    const float4* w34 = (const float4*)(w_att + 2 * Hdim) + q * 4;
    float acc = 0.f;
#pragma unroll
    for (int k = 0; k < 4; ++k) {
      float4 d = dj[k];
      float4 w = w34[k];
      acc = fmaf(d.x, w.x, acc);
      acc = fmaf(d.y, w.y, acc);
      acc = fmaf(d.z, w.z, acc);
      acc = fmaf(d.w, w.w, acc);
    }
    acc += __shfl_xor_sync(0xffffffffu, acc, 1);
    acc += __shfl_xor_sync(0xffffffffu, acc, 2);
    if (q == 0) {
      float s = base + g_t2[b * Sdim + ((j + 1) & (Sdim - 1))] + acc;
      s = (s >= 0.f) ? s : 0.01f * s;
      if (deprow[j] <= 0) s = -1e9f;
      sm_s[j] = s;
    }
  }
  __syncthreads();

  float sv = (tid < Sdim) ? sm_s[tid] : -1e30f;
  float m = blockReduceMax32(sv, sm_red);
  float e = (tid < Sdim) ? expf(sv - m) : 0.f;
  float sum = blockReduceSum32(e, sm_red);
  if (tid < Sdim) {
    float p = e / sum;
    sm_p[tid] = p;
    g_attn[slot * Sdim + tid] = p;
  }
  __syncthreads();

  {
    int d = tid & 63, part = tid >> 6;
    float ad = 0.f;
    const float* dp = sD + (size_t)(part * 16) * 68 + d;
#pragma unroll
    for (int jj = 0; jj < 16; ++jj) ad = fmaf(sm_p[part * 16 + jj], dp[jj * 68], ad);
    sm_agg[tid] = ad;
    __syncthreads();
    if (tid < Ddim) {
      float t = 0.f;
#pragma unroll
      for (int p = 0; p < 16; ++p) t += sm_agg[p * 64 + tid];
      g_D64[slot * Ddim + tid] = t;
    }
  }
  if (tid == 0) {
    g_valid[slot] = 1;
    g_rowi[slot] = i;
  }
}

// v partials: grid (128, 8), block 192.
__global__ void __launch_bounds__(192) k_v(const float* __restrict__ bert) {
  int slot = blockIdx.x, g = blockIdx.y;
  int b = slot >> 3;
  int tid = threadIdx.x;
  __shared__ float sp[32];
  if (tid < 32) sp[tid] = g_attn[slot * Sdim + g * 32 + tid];
  __syncthreads();
  const float4* bb4 = (const float4*)(bert + (size_t)b * Sdim * Hdim);
  float4 acc = make_float4(0.f, 0.f, 0.f, 0.f);
#pragma unroll 8
  for (int jj = 0; jj < 32; ++jj) {
    int j = g * 32 + jj;
    float p = sp[jj];
    float4 bv = bb4[(size_t)((j + 1) & (Sdim - 1)) * H4 + tid];
    acc.x = fmaf(p, bv.x, acc.x);
    acc.y = fmaf(p, bv.y, acc.y);
    acc.z = fmaf(p, bv.z, acc.z);
    acc.w = fmaf(p, bv.w, acc.w);
  }
  ((float4*)g_P)[(size_t)(PV_OFF + g * NSLOT + slot) * H4 + tid] = acc;
}

// Sum v partials -> g_Xv. grid 128, block 192.
__global__ void __launch_bounds__(192) k_vsum() {
  int slot = blockIdx.x;
  int tid = threadIdx.x;
  float4 v = make_float4(0.f, 0.f, 0.f, 0.f);
#pragma unroll
  for (int g = 0; g < 8; ++g) {
    float4 p = ((const float4*)g_P)[(size_t)(PV_OFF + g * NSLOT + slot) * H4 + tid];
    v.x += p.x;
    v.y += p.y;
    v.z += p.z;
    v.w += p.w;
  }
  ((float4*)g_Xv)[slot * H4 + tid] = v;
}

#define FMAK4(C, WV, A0, A1, A2, A3)  \
  do {                                \
    unsigned long long s;             \
    s = splat2(x0.C);                 \
    ffma2(A0##l, s, (WV).x);          \
    ffma2(A0##h, s, (WV).y);          \
    s = splat2(x1.C);                 \
    ffma2(A1##l, s, (WV).x);          \
    ffma2(A1##h, s, (WV).y);          \
    s = splat2(x2.C);                 \
    ffma2(A2##l, s, (WV).x);          \
    ffma2(A2##h, s, (WV).y);          \
    s = splat2(x3.C);                 \
    ffma2(A3##l, s, (WV).x);          \
    ffma2(A3##h, s, (WV).y);          \
  } while (0)

// cp.async smem-staged partial GEMM, 4 cols x 8 rows/thread, tile 64x128.
// grid (12, 1, ksplit). Partials -> P[(z*128 + r)*Hdim + h].
template <int KS, int LDX, int NIT>
__global__ void __launch_bounds__(256) k_sgemm(const float* __restrict__ X,
                                               const float* __restrict__ W,
                                               float* __restrict__ P) {
  static_assert(KS == NIT * 32, "");
  __shared__ __align__(16) float sW[2][32 * 64];
  __shared__ __align__(16) float sX[2][128 * 32];

  int tid = threadIdx.x;
  int ct = tid & 15, rt = tid >> 4;
  int hb = blockIdx.x * 64;
  int z = blockIdx.z;

  const float* Wg = W + (size_t)z * KS * Hdim + hb;
  const float* Xg = X + (size_t)z * KS;

  int wi = tid >> 4, wj = (tid & 15) * 4;
  int xi = tid >> 3, xj = (tid & 7) * 4;
  unsigned int sw0 = saddr_of(&sW[0][0]);
  unsigned int sx0 = saddr_of(&sX[0][0]);

#define LOAD_STAGE(stage, buf)                                                  \
  do {                                                                          \
    int k0 = (stage) * 32;                                                      \
    unsigned int swb = sw0 + (buf) * (32 * 64 * 4);                             \
    unsigned int sxb = sx0 + (buf) * (128 * 32 * 4);                            \
    cpasync16(swb + (wi * 64 + wj) * 4, Wg + (size_t)(k0 + wi) * Hdim + wj);    \
    cpasync16(swb + ((wi + 16) * 64 + wj) * 4,                                  \
              Wg + (size_t)(k0 + wi + 16) * Hdim + wj);                         \
    cpasync16(sxb + (xi * 32 + xj) * 4, Xg + (size_t)xi * LDX + k0 + xj);       \
    cpasync16(sxb + ((xi + 32) * 32 + xj) * 4,                                  \
              Xg + (size_t)(xi + 32) * LDX + k0 + xj);                          \
    cpasync16(sxb + ((xi + 64) * 32 + xj) * 4,                                  \
              Xg + (size_t)(xi + 64) * LDX + k0 + xj);                          \
    cpasync16(sxb + ((xi + 96) * 32 + xj) * 4,                                  \
              Xg + (size_t)(xi + 96) * LDX + k0 + xj);                          \
    cpasync_commit();                                                           \
  } while (0)

  LOAD_STAGE(0, 0);
  if (NIT > 1) LOAD_STAGE(1, 1);

  unsigned long long a0l = 0, a0h = 0, a1l = 0, a1h = 0;
  unsigned long long a2l = 0, a2h = 0, a3l = 0, a3h = 0;
  unsigned long long a4l = 0, a4h = 0, a5l = 0, a5h = 0;
  unsigned long long a6l = 0, a6h = 0, a7l = 0, a7h = 0;
  int r0 = rt * 8;

#pragma unroll 1
  for (int it = 0; it < NIT; ++it) {
    if (it < NIT - 1)
      cpasync_wait1();
    else
      cpasync_wait0();
    __syncthreads();
    int buf = it & 1;
    const float* xbase = &sX[buf][0];
    const float* wb = &sW[buf][ct * 4];
#pragma unroll
    for (int k4 = 0; k4 < 8; ++k4) {
      ulonglong2 w0 = *(const ulonglong2*)(wb + (k4 * 4 + 0) * 64);
      ulonglong2 w1 = *(const ulonglong2*)(wb + (k4 * 4 + 1) * 64);
      ulonglong2 w2 = *(const ulonglong2*)(wb + (k4 * 4 + 2) * 64);
      ulonglong2 w3 = *(const ulonglong2*)(wb + (k4 * 4 + 3) * 64);
      {
        float4 x0 = *(const float4*)(xbase + (r0 + 0) * 32 + k4 * 4);
        float4 x1 = *(const float4*)(xbase + (r0 + 1) * 32 + k4 * 4);
        float4 x2 = *(const float4*)(xbase + (r0 + 2) * 32 + k4 * 4);
        float4 x3 = *(const float4*)(xbase + (r0 + 3) * 32 + k4 * 4);
        FMAK4(x, w0, a0, a1, a2, a3);
        FMAK4(y, w1, a0, a1, a2, a3);
        FMAK4(z, w2, a0, a1, a2, a3);
        FMAK4(w, w3, a0, a1, a2, a3);
      }
      {
        float4 x0 = *(const float4*)(xbase + (r0 + 4) * 32 + k4 * 4);
        float4 x1 = *(const float4*)(xbase + (r0 + 5) * 32 + k4 * 4);
        float4 x2 = *(const float4*)(xbase + (r0 + 6) * 32 + k4 * 4);
        float4 x3 = *(const float4*)(xbase + (r0 + 7) * 32 + k4 * 4);
        FMAK4(x, w0, a4, a5, a6, a7);
        FMAK4(y, w1, a4, a5, a6, a7);
        FMAK4(z, w2, a4, a5, a6, a7);
        FMAK4(w, w3, a4, a5, a6, a7);
      }
    }
    __syncthreads();
    if (it + 2 < NIT) LOAD_STAGE(it + 2, buf);
  }
#undef LOAD_STAGE

  float* pr = P + ((size_t)(z * NSLOT + r0)) * Hdim + hb + ct * 4;
#define STORE_ROW(q, A)                                                  \
  {                                                                      \
    float2 fl = u2f(A##l), fh = u2f(A##h);                               \
    *(float4*)(pr + (q)*Hdim) = make_float4(fl.x, fl.y, fh.x, fh.y);     \
  }
  STORE_ROW(0, a0)
  STORE_ROW(1, a1)
  STORE_ROW(2, a2)
  STORE_ROW(3, a3)
  STORE_ROW(4, a4)
  STORE_ROW(5, a5)
  STORE_ROW(6, a6)
  STORE_ROW(7, a7)
#undef STORE_ROW
}

// Epilogue: sum NZ1 partials at row OFF1 (+NZ2 at OFF2), route per MODE.
// MODE 0: +bias -> g_A; 1: +bias -> g_Z; 2: -> g_N; 3: scatter valid -> out.
template <int NZ1, int OFF1, int NZ2, int OFF2, int MODE>
__global__ void __launch_bounds__(192) k_epi(const float* __restrict__ bias,
                                             float* __restrict__ outp) {
  int r = blockIdx.x;
  if (MODE == 3 && !g_valid[r]) return;
  int h = threadIdx.x * 4;
  float4 v = make_float4(0.f, 0.f, 0.f, 0.f);
#pragma unroll
  for (int zz = 0; zz < NZ1; ++zz) {
    const float4 p =
        *(const float4*)(g_P + (size_t)(OFF1 + zz * NSLOT + r) * Hdim + h);
    v.x += p.x;
    v.y += p.y;
    v.z += p.z;
    v.w += p.w;
  }
#pragma unroll
  for (int zz = 0; zz < NZ2; ++zz) {
    const float4 p =
        *(const float4*)(g_P + (size_t)(OFF2 + zz * NSLOT + r) * Hdim + h);
    v.x += p.x;
    v.y += p.y;
    v.z += p.z;
    v.w += p.w;
  }
  if (MODE <= 1) {
    const float4 bb = *(const float4*)(bias + h);
    v.x += bb.x;
    v.y += bb.y;
    v.z += bb.z;
    v.w += bb.w;
  }
  if (MODE == 0)
    *(float4*)(g_A + (size_t)r * Hdim + h) = v;
  else if (MODE == 1)
    *(float4*)(g_Z + (size_t)r * Hdim + h) = v;
  else if (MODE == 2)
    *(float4*)(g_N + (size_t)r * Hdim + h) = v;
  else {
    int bb = r >> 3;
    int o = (g_rowi[r] + 1) & (Sdim - 1);
    *(float4*)(outp + ((size_t)(bb * Sdim + o)) * Hdim + h) = v;
  }
}

extern "C" void kernel_launch(void* const* d_in, const int* in_sizes, int n_in,
                              void* d_out, int out_size) {
  const float* bert = (const float*)d_in[0];
  const float* dta = (const float*)d_in[1];
  const int* deprel = (const int*)d_in[2];
  const int* asp_s = (const int*)d_in[3];
  const int* asp_e = (const int*)d_in[4];
  const float* Wz = (const float*)d_in[5];
  const float* bz = (const float*)d_in[6];
  const float* watt = (const float*)d_in[7];
  const float* batt = (const float*)d_in[8];
  const float* Wf = (const float*)d_in[9];
  const float* Wh = (const float*)d_in[10];
  float* out = (float*)d_out;

  float* P;
  float* Xv;
  float* Xn;
  float* A;
  float* Z;
  float* N;
  float* D64;
  cudaGetSymbolAddress((void**)&P, g_P);
  cudaGetSymbolAddress((void**)&Xv, g_Xv);
  cudaGetSymbolAddress((void**)&Xn, g_Xn);
  cudaGetSymbolAddress((void**)&A, g_A);
  cudaGetSymbolAddress((void**)&Z, g_Z);
  cudaGetSymbolAddress((void**)&N, g_N);
  cudaGetSymbolAddress((void**)&D64, g_D64);

  // Fork side streams.
  cudaEventRecord(g_evFork, 0);
  cudaStreamWaitEvent(g_s2, g_evFork, 0);
  cudaStreamWaitEvent(g_s3, g_evFork, 0);

  // s3: bulk copy bert -> out.
  k_copy<<<(Bdim * Sdim * Hdim / 4) / 256, 256, 0, g_s3>>>((const float4*)bert,
                                                           (float4*)out);
  cudaEventRecord(g_evCopy, g_s3);

  // s2: z-path (independent of attention): gather -> @Wz -> +bz -> @Wh[H:].
  k_gather<<<NSLOT, 192, 0, g_s2>>>(bert, asp_s);
  k_sgemm<64, Hdim, 2><<<dim3(12, 1, 12), 256, 0, g_s2>>>(Xn, Wz,
                                                          P + (size_t)P0B_OFF * Hdim);
  k_epi<12, P0B_OFF, 0, 0, 1><<<NSLOT, 192, 0, g_s2>>>(bz, nullptr);
  k_sgemm<64, Hdim, 2><<<dim3(12, 1, 12), 256, 0, g_s2>>>(
      Z, Wh + (size_t)Hdim * Hdim, P + (size_t)P2B_OFF * Hdim);
  cudaEventRecord(g_evZ, g_s2);

  // s0: attention critical path.
  k_pre<<<769, 256>>>(Wz, bz, watt);
  k_t2d<<<(Bdim * Sdim) / 8, 256>>>(bert);
  k_att<<<dim3(Bdim, 8), 1024, ATT_SMEM_FLOATS * 4>>>(bert, dta, deprel, asp_s,
                                                      asp_e, watt, batt);
  // agg_d @ Wf[768:] (K=64) — depends only on k_att.
  k_sgemm<32, Ddim, 1><<<dim3(12, 1, 2), 256>>>(D64, Wf + (size_t)Hdim * Hdim,
                                                P + (size_t)P1B_OFF * Hdim);
  k_v<<<dim3(NSLOT, 8), 192>>>(bert);
  k_vsum<<<NSLOT, 192>>>();
  // v @ Wz (K=768, z=24)
  k_sgemm<32, Hdim, 1><<<dim3(12, 1, 24), 256>>>(Xv, Wz,
                                                 P + (size_t)P0A_OFF * Hdim);
  k_epi<24, P0A_OFF, 0, 0, 0><<<NSLOT, 192>>>(bz, nullptr);  // -> agg_z
  // agg_z @ Wf[:768]
  k_sgemm<32, Hdim, 1><<<dim3(12, 1, 24), 256>>>(A, Wf, P + (size_t)P1A_OFF * Hdim);
  k_epi<24, P1A_OFF, 2, P1B_OFF, 2><<<NSLOT, 192>>>(nullptr, nullptr);  // -> nrep
  // nrep @ Wh[:768]
  k_sgemm<32, Hdim, 1><<<dim3(12, 1, 24), 256>>>(N, Wh, P + (size_t)P2A_OFF * Hdim);

  // Join: z-path partials + bulk copy must be complete before final scatter.
  cudaStreamWaitEvent(0, g_evZ, 0);
  cudaStreamWaitEvent(0, g_evCopy, 0);
  k_epi<24, P2A_OFF, 12, P2B_OFF, 3><<<NSLOT, 192>>>(nullptr, out);
}